// round 1
// baseline (speedup 1.0000x reference)
#include <cuda_runtime.h>
#include <cuda_bf16.h>
#include <cstdint>

// FSSwishLayer: 16-step spiking-threshold scan.
//   v = x; out = 0
//   for t in 0..15: z = (v - T[t] > 0); v -= z*h[t]; out += z*d[t]
// out is the result.
//
// Strategy: pack (v, out) into one 64-bit register pair and perform both
// conditional updates with a single predicated add.rn.f32x2 (Blackwell packed
// fp32). Inner step = FSETP + @P FADD2 -> 1 fma-pipe instr per step per
// element instead of 2. Memory is streamed as float4 (vectorized 128-bit
// LDG/STG), grid-stride so the 48 scalar parameter loads amortize.

#define NSTEPS 16

__device__ __forceinline__ void fs_step(unsigned long long& s, float Tt,
                                        unsigned long long Ct) {
    // s = packed {v (lo), out (hi)}; Ct = packed {-h (lo), d (hi)}
    asm("{\n\t"
        ".reg .pred p;\n\t"
        ".reg .f32 v, o;\n\t"
        "mov.b64 {v, o}, %0;\n\t"       // extract v (lo half); coalesces in SASS
        "setp.gt.f32 p, v, %1;\n\t"     // z = v > T  (== v - T > 0 in fp32)
        "@p add.rn.f32x2 %0, %0, %2;\n\t" // v += -h; out += d   (one packed add)
        "}"
        : "+l"(s)
        : "f"(Tt), "l"(Ct));
}

__global__ void __launch_bounds__(256)
fs_swish_kernel(const float4* __restrict__ x, float4* __restrict__ out,
                const float* __restrict__ h, const float* __restrict__ d,
                const float* __restrict__ T, int n4) {
    // Load scalar params into registers once per thread.
    float Tt[NSTEPS];
    unsigned long long Ct[NSTEPS];
#pragma unroll
    for (int t = 0; t < NSTEPS; t++) {
        Tt[t] = __ldg(T + t);
        unsigned int lo = __float_as_uint(-__ldg(h + t));
        unsigned int hi = __float_as_uint(__ldg(d + t));
        Ct[t] = ((unsigned long long)hi << 32) | (unsigned long long)lo;
    }

    const int stride = gridDim.x * blockDim.x;
    for (int i = blockIdx.x * blockDim.x + threadIdx.x; i < n4; i += stride) {
        float4 xv = x[i];

        // 4 independent chains (ILP hides the 13-cyc FSETP->guard latency).
        unsigned long long s0 = (unsigned long long)__float_as_uint(xv.x);
        unsigned long long s1 = (unsigned long long)__float_as_uint(xv.y);
        unsigned long long s2 = (unsigned long long)__float_as_uint(xv.z);
        unsigned long long s3 = (unsigned long long)__float_as_uint(xv.w);

#pragma unroll
        for (int t = 0; t < NSTEPS; t++) {
            fs_step(s0, Tt[t], Ct[t]);
            fs_step(s1, Tt[t], Ct[t]);
            fs_step(s2, Tt[t], Ct[t]);
            fs_step(s3, Tt[t], Ct[t]);
        }

        float4 ov;
        ov.x = __uint_as_float((unsigned int)(s0 >> 32));
        ov.y = __uint_as_float((unsigned int)(s1 >> 32));
        ov.z = __uint_as_float((unsigned int)(s2 >> 32));
        ov.w = __uint_as_float((unsigned int)(s3 >> 32));
        out[i] = ov;
    }
}

extern "C" void kernel_launch(void* const* d_in, const int* in_sizes, int n_in,
                              void* d_out, int out_size) {
    const float* x = (const float*)d_in[0];
    const float* h = (const float*)d_in[1];
    const float* d = (const float*)d_in[2];
    const float* T = (const float*)d_in[3];

    int n  = in_sizes[0];   // 67,108,864 elements (divisible by 4)
    int n4 = n >> 2;

    // Grid-stride: few enough threads that per-thread param loads amortize,
    // enough warps (~16/SM at this occupancy) to cover LDG + FSETP latency.
    const int threads = 256;
    const int blocks  = 148 * 16;  // 2368 blocks, ~27 float4 iters/thread

    fs_swish_kernel<<<blocks, threads>>>(
        (const float4*)x, (float4*)d_out, h, d, T, n4);
}